// round 5
// baseline (speedup 1.0000x reference)
#include <cuda_runtime.h>
#include <cuda_bf16.h>
#include <cstdint>

// ---------------------------------------------------------------------------
// MLA prefill, fp32 with packed f32x2 FFMA (sm_103a FFMA2 path).
// B=2, S=2048, DIM=2048, H=16, Q_LORA=512, KV_LORA=512,
// D_NOPE=128, D_ROPE=64, D_V=128, D_QK=192.
// ---------------------------------------------------------------------------

namespace {
constexpr int Bc = 2, Sc = 2048, DIMc = 2048, Hc = 16;
constexpr int Q_LORA = 512, KV_LORA = 512;
constexpr int D_NOPE = 128, D_ROPE = 64, D_V = 128, D_QK = 192;
constexpr int ROWS = Bc * Sc;        // 4096 tokens
constexpr int KV_W = D_NOPE + D_V;   // 256
}

// Scratch (static device arrays: allocation-free per harness rules)
__device__ float g_qa  [ROWS * Q_LORA];
__device__ float g_kva [ROWS * (KV_LORA + D_ROPE)];
__device__ float g_qln [ROWS * Q_LORA];
__device__ float g_kvln[ROWS * KV_LORA];
__device__ float g_kpe [ROWS * D_ROPE];
__device__ float g_q   [ROWS * Hc * D_QK];
__device__ float g_kv  [ROWS * Hc * KV_W];
__device__ float g_ao  [ROWS * Hc * D_V];

// ---------------------------------------------------------------------------
// f32x2 packed helpers
// ---------------------------------------------------------------------------
__device__ __forceinline__ void ffma2(uint64_t& d, uint64_t a, uint64_t b) {
    asm("fma.rn.f32x2 %0, %1, %2, %0;" : "+l"(d) : "l"(a), "l"(b));
}
__device__ __forceinline__ void fmul2(uint64_t& d, uint64_t a) {
    asm("mul.rn.f32x2 %0, %0, %1;" : "+l"(d) : "l"(a));
}
__device__ __forceinline__ uint64_t dup2(float x) {
    uint64_t r; asm("mov.b64 %0, {%1, %1};" : "=l"(r) : "f"(x)); return r;
}
__device__ __forceinline__ uint64_t pk2(float x, float y) {
    uint64_t r; asm("mov.b64 %0, {%1, %2};" : "=l"(r) : "f"(x), "f"(y)); return r;
}
__device__ __forceinline__ float2 unpk(uint64_t p) {
    float2 r; asm("mov.b64 {%0, %1}, %2;" : "=f"(r.x), "=f"(r.y) : "l"(p)); return r;
}

// ---------------------------------------------------------------------------
// GEMM: C[M,N] = A[M,K] @ W[K,N] (+ bias). 128x128 tile, BK=8, 256 threads,
// 8x8 per thread, inner product via FFMA2 packed over N (B pairs natural,
// A duplicated into both halves).
// ---------------------------------------------------------------------------
__global__ __launch_bounds__(256, 2) void gemm_kernel(
    const float* __restrict__ A, const float* __restrict__ W,
    const float* __restrict__ bias, float* __restrict__ C,
    int M, int N, int K)
{
    constexpr int BM = 128, BN = 128, BK = 8;
    __shared__ float As[BK][BM];
    __shared__ float Bs[BK][BN];

    const int tid = threadIdx.x;
    const int ty = tid >> 4, tx = tid & 15;
    const int row0 = blockIdx.y * BM;
    const int col0 = blockIdx.x * BN;

    const int a_m = tid >> 1;
    const int a_k = (tid & 1) << 2;
    const int b_k = tid >> 5;
    const int b_n = (tid & 31) << 2;

    uint64_t acc2[8][4];   // [row i][col-pair jp]; pairs over N
#pragma unroll
    for (int i = 0; i < 8; i++)
#pragma unroll
        for (int jp = 0; jp < 4; jp++) acc2[i][jp] = 0ull;

    const float* Aptr = A + (size_t)(row0 + a_m) * K + a_k;

    for (int k0 = 0; k0 < K; k0 += BK) {
        float4 av = *(const float4*)(Aptr + k0);
        As[a_k + 0][a_m] = av.x;
        As[a_k + 1][a_m] = av.y;
        As[a_k + 2][a_m] = av.z;
        As[a_k + 3][a_m] = av.w;

        const int gn = col0 + b_n;
        float4 bv = make_float4(0.f, 0.f, 0.f, 0.f);
        if (gn < N) bv = *(const float4*)(W + (size_t)(k0 + b_k) * N + gn);
        *(float4*)&Bs[b_k][b_n] = bv;
        __syncthreads();

#pragma unroll
        for (int kk = 0; kk < BK; kk++) {
            float4 a0 = *(const float4*)&As[kk][ty * 4];
            float4 a1 = *(const float4*)&As[kk][ty * 4 + 64];
            ulonglong2 bl0 = *(const ulonglong2*)&Bs[kk][tx * 4];
            ulonglong2 bl1 = *(const ulonglong2*)&Bs[kk][tx * 4 + 64];
            uint64_t bp[4] = {bl0.x, bl0.y, bl1.x, bl1.y};
            uint64_t ad[8];
            ad[0] = dup2(a0.x); ad[1] = dup2(a0.y);
            ad[2] = dup2(a0.z); ad[3] = dup2(a0.w);
            ad[4] = dup2(a1.x); ad[5] = dup2(a1.y);
            ad[6] = dup2(a1.z); ad[7] = dup2(a1.w);
#pragma unroll
            for (int i = 0; i < 8; i++)
#pragma unroll
                for (int jp = 0; jp < 4; jp++)
                    ffma2(acc2[i][jp], ad[i], bp[jp]);
        }
        __syncthreads();
    }

#pragma unroll
    for (int i = 0; i < 8; i++) {
        const int r = row0 + ty * 4 + (i < 4 ? i : 60 + i);
#pragma unroll
        for (int jj = 0; jj < 2; jj++) {
            const int c = col0 + tx * 4 + jj * 64;
            if (c < N) {
                float2 lo = unpk(acc2[i][jj * 2 + 0]);
                float2 hi = unpk(acc2[i][jj * 2 + 1]);
                float4 v = make_float4(lo.x, lo.y, hi.x, hi.y);
                if (bias) {
                    v.x += bias[c + 0]; v.y += bias[c + 1];
                    v.z += bias[c + 2]; v.w += bias[c + 3];
                }
                *(float4*)(C + (size_t)r * N + c) = v;
            }
        }
    }
}

// ---------------------------------------------------------------------------
// Fused: rmsnorm(q_a) -> g_qln; rmsnorm(kv_a[:,:512]) -> g_kvln;
// rope(kv_a[:,512:576]) -> g_kpe.  One block per token row.
// ---------------------------------------------------------------------------
__global__ __launch_bounds__(256) void norm_rope_kernel(
    const float* __restrict__ qnw, const float* __restrict__ kvnw,
    const float* __restrict__ cos_t, const float* __restrict__ sin_t)
{
    const int row = blockIdx.x;
    const int tid = threadIdx.x;
    const int s = row & (Sc - 1);
    __shared__ float red[8];

    const float* qr = g_qa + (size_t)row * Q_LORA;
    float v0 = qr[tid], v1 = qr[tid + 256];
    float ss = v0 * v0 + v1 * v1;
#pragma unroll
    for (int o = 16; o; o >>= 1) ss += __shfl_xor_sync(0xffffffffu, ss, o);
    if ((tid & 31) == 0) red[tid >> 5] = ss;
    __syncthreads();
    float tot = 0.f;
#pragma unroll
    for (int i = 0; i < 8; i++) tot += red[i];
    float scl = rsqrtf(tot * (1.0f / Q_LORA) + 1e-6f);
    g_qln[(size_t)row * Q_LORA + tid]       = v0 * scl * qnw[tid];
    g_qln[(size_t)row * Q_LORA + tid + 256] = v1 * scl * qnw[tid + 256];
    __syncthreads();

    const float* kr = g_kva + (size_t)row * (KV_LORA + D_ROPE);
    float w0 = kr[tid], w1 = kr[tid + 256];
    float ss2 = w0 * w0 + w1 * w1;
#pragma unroll
    for (int o = 16; o; o >>= 1) ss2 += __shfl_xor_sync(0xffffffffu, ss2, o);
    if ((tid & 31) == 0) red[tid >> 5] = ss2;
    __syncthreads();
    float tot2 = 0.f;
#pragma unroll
    for (int i = 0; i < 8; i++) tot2 += red[i];
    float scl2 = rsqrtf(tot2 * (1.0f / KV_LORA) + 1e-6f);
    g_kvln[(size_t)row * KV_LORA + tid]       = w0 * scl2 * kvnw[tid];
    g_kvln[(size_t)row * KV_LORA + tid + 256] = w1 * scl2 * kvnw[tid + 256];

    if (tid < 32) {
        float x0 = kr[KV_LORA + 2 * tid];
        float x1 = kr[KV_LORA + 2 * tid + 1];
        float c = cos_t[s * 32 + tid], sn = sin_t[s * 32 + tid];
        g_kpe[(size_t)row * D_ROPE + 2 * tid]     = x0 * c - x1 * sn;
        g_kpe[(size_t)row * D_ROPE + 2 * tid + 1] = x0 * sn + x1 * c;
    }
}

// ---------------------------------------------------------------------------
// RoPE on q_pe (last 64 of each head's 192), in place on g_q.
// ---------------------------------------------------------------------------
__global__ __launch_bounds__(256) void rope_q_kernel(
    const float* __restrict__ cos_t, const float* __restrict__ sin_t)
{
    const int idx = blockIdx.x * 256 + threadIdx.x;
    const int i = idx & 31;
    const int h = (idx >> 5) & 15;
    const int row = idx >> 9;
    const int s = row & (Sc - 1);
    float* p = g_q + ((size_t)row * Hc + h) * D_QK + D_NOPE + 2 * i;
    float x0 = p[0], x1 = p[1];
    float c = cos_t[s * 32 + i], sn = sin_t[s * 32 + i];
    p[0] = x0 * c - x1 * sn;
    p[1] = x0 * sn + x1 * c;
}

// ---------------------------------------------------------------------------
// Flash attention, fp32 + FFMA2. One block per (q-tile 64, head, batch).
// Row-major Q/K smem; K chunk-XOR-swizzled for conflict-free vector loads;
// scores packed over the d reduction (even/odd partials in one f32x2 reg).
// Softmax entirely in registers + half-warp shuffles.
// ---------------------------------------------------------------------------
namespace {
constexpr int TQ = 64, TK = 64;
constexpr int QROW = 192;           // Q/K row length (floats)
constexpr int PST = 66;             // P tile stride
constexpr int QS_F = TQ * QROW;     // 12288
constexpr int KS_F = TK * QROW;     // 12288
constexpr int VS_F = TK * D_V;      // 8192
constexpr int PS_F = TQ * PST;      // 4224
constexpr int ATT_SMEM_FLOATS = QS_F + KS_F + VS_F + PS_F;
constexpr float QK_SCALE = 0.07216878364870322f;  // 192^-0.5
}

__global__ __launch_bounds__(256) void attn_kernel()
{
    extern __shared__ float sm[];
    float* Qs = sm;            // [64][192] row-major (pre-scaled)
    float* Ks = Qs + QS_F;     // [64][192] row-major, chunk-swizzled
    float* Vs = Ks + KS_F;     // [64][128] row-major
    float* Ps = Vs + VS_F;     // [64][66]

    const int tid = threadIdx.x;
    const int ty = tid >> 4, tx = tid & 15;
    const int bq = gridDim.x - 1 - blockIdx.x;   // heavy tiles launch first
    const int h = blockIdx.y;
    const int b = blockIdx.z;
    const int s0 = bq * TQ;
    const int xs = tx & 7;

    // Load Q tile (pre-scaled), row-major
    const float* qbase = g_q + (((size_t)b * Sc + s0) * Hc + h) * D_QK;
    for (int idx = tid; idx < TQ * 48; idx += 256) {
        int r = idx / 48, c4 = idx - r * 48;
        float4 v = *(const float4*)(qbase + (size_t)r * Hc * D_QK + 4 * c4);
        v.x *= QK_SCALE; v.y *= QK_SCALE; v.z *= QK_SCALE; v.w *= QK_SCALE;
        *(float4*)&Qs[r * QROW + 4 * c4] = v;
    }

    float m_i[4], l_i[4];
    uint64_t acc2[4][4];
#pragma unroll
    for (int i = 0; i < 4; i++) {
        m_i[i] = -1e30f; l_i[i] = 0.f;
#pragma unroll
        for (int jp = 0; jp < 4; jp++) acc2[i][jp] = 0ull;
    }

    const float* kvbase  = g_kv  + ((size_t)b * Sc * Hc + h) * KV_W;
    const float* kpebase = g_kpe + (size_t)b * Sc * D_ROPE;

    for (int jt = 0; jt <= bq; jt++) {
        const int t0 = jt * TK;
        __syncthreads();   // smem reuse (and Q visibility on iter 0)

        // K nope part: rows c, chunks d4=0..31, XOR-swizzled
        for (int idx = tid; idx < TK * 32; idx += 256) {
            int c = idx >> 5, d4 = idx & 31;
            float4 v = *(const float4*)(kvbase + (size_t)(t0 + c) * Hc * KV_W + 4 * d4);
            *(float4*)&Ks[c * QROW + 4 * (d4 ^ ((c >> 2) & 7))] = v;
        }
        // K rope part: chunks d4=32..47
        for (int idx = tid; idx < TK * 16; idx += 256) {
            int c = idx >> 4, dq = idx & 15;
            float4 v = *(const float4*)(kpebase + (size_t)(t0 + c) * D_ROPE + 4 * dq);
            *(float4*)&Ks[c * QROW + 4 * ((32 + dq) ^ ((c >> 2) & 7))] = v;
        }
        // V tile, row-major
        for (int idx = tid; idx < TK * 32; idx += 256) {
            int c = idx >> 5, d4 = idx & 31;
            float4 v = *(const float4*)(kvbase + (size_t)(t0 + c) * Hc * KV_W + D_NOPE + 4 * d4);
            *(float4*)&Vs[c * D_V + 4 * d4] = v;
        }
        __syncthreads();

        // ---- Scores: packed over d (even/odd partials per f32x2 reg) ----
        uint64_t sf2[4][4];
#pragma unroll
        for (int i = 0; i < 4; i++)
#pragma unroll
            for (int j = 0; j < 4; j++) sf2[i][j] = 0ull;

#pragma unroll 4
        for (int cc = 0; cc < 48; cc++) {
            ulonglong2 qv[4];
#pragma unroll
            for (int i = 0; i < 4; i++)
                qv[i] = *(const ulonglong2*)&Qs[(ty * 4 + i) * QROW + 4 * cc];
            const int koff = 4 * (cc ^ xs);
            ulonglong2 kv4[4];
#pragma unroll
            for (int j = 0; j < 4; j++)
                kv4[j] = *(const ulonglong2*)&Ks[(tx * 4 + j) * QROW + koff];
#pragma unroll
            for (int i = 0; i < 4; i++)
#pragma unroll
                for (int j = 0; j < 4; j++) {
                    ffma2(sf2[i][j], qv[i].x, kv4[j].x);
                    ffma2(sf2[i][j], qv[i].y, kv4[j].y);
                }
        }

        float s[4][4];
#pragma unroll
        for (int i = 0; i < 4; i++)
#pragma unroll
            for (int j = 0; j < 4; j++) {
                float2 t = unpk(sf2[i][j]);
                s[i][j] = t.x + t.y;
            }

        // Causal mask (only the diagonal tile needs it)
        if (jt == bq) {
#pragma unroll
            for (int i = 0; i < 4; i++) {
                const int sg = s0 + ty * 4 + i;
#pragma unroll
                for (int j = 0; j < 4; j++)
                    if (t0 + tx * 4 + j > sg) s[i][j] = -1e30f;
            }
        }

        // ---- Online softmax in registers, half-warp shuffles ----
#pragma unroll
        for (int i = 0; i < 4; i++) {
            float mx = fmaxf(fmaxf(s[i][0], s[i][1]), fmaxf(s[i][2], s[i][3]));
            mx = fmaxf(mx, __shfl_xor_sync(0xffffffffu, mx, 1));
            mx = fmaxf(mx, __shfl_xor_sync(0xffffffffu, mx, 2));
            mx = fmaxf(mx, __shfl_xor_sync(0xffffffffu, mx, 4));
            mx = fmaxf(mx, __shfl_xor_sync(0xffffffffu, mx, 8));
            float mn = fmaxf(m_i[i], mx);
            float f = __expf(m_i[i] - mn);
            m_i[i] = mn;
            float p0 = __expf(s[i][0] - mn);
            float p1 = __expf(s[i][1] - mn);
            float p2 = __expf(s[i][2] - mn);
            float p3 = __expf(s[i][3] - mn);
            float sum = (p0 + p1) + (p2 + p3);
            sum += __shfl_xor_sync(0xffffffffu, sum, 1);
            sum += __shfl_xor_sync(0xffffffffu, sum, 2);
            sum += __shfl_xor_sync(0xffffffffu, sum, 4);
            sum += __shfl_xor_sync(0xffffffffu, sum, 8);
            l_i[i] = l_i[i] * f + sum;
            uint64_t fd = dup2(f);
#pragma unroll
            for (int jp = 0; jp < 4; jp++) fmul2(acc2[i][jp], fd);
            *(uint64_t*)&Ps[(ty * 4 + i) * PST + tx * 4]     = pk2(p0, p1);
            *(uint64_t*)&Ps[(ty * 4 + i) * PST + tx * 4 + 2] = pk2(p2, p3);
        }
        __syncwarp();   // P rows stay within this half-warp

        // ---- P @ V: packed over d_v (V pairs natural), p duplicated ----
#pragma unroll 2
        for (int c = 0; c < TK; c++) {
            ulonglong2 v01 = *(const ulonglong2*)&Vs[c * D_V + tx * 8];
            ulonglong2 v23 = *(const ulonglong2*)&Vs[c * D_V + tx * 8 + 4];
            uint64_t vp[4] = {v01.x, v01.y, v23.x, v23.y};
#pragma unroll
            for (int i = 0; i < 4; i++) {
                uint64_t pd = dup2(Ps[(ty * 4 + i) * PST + c]);
#pragma unroll
                for (int jp = 0; jp < 4; jp++) ffma2(acc2[i][jp], pd, vp[jp]);
            }
        }
    }

    // Epilogue
#pragma unroll
    for (int i = 0; i < 4; i++) {
        const int sg = s0 + ty * 4 + i;
        const float inv = 1.0f / l_i[i];
        float2 o0 = unpk(acc2[i][0]), o1 = unpk(acc2[i][1]);
        float2 o2 = unpk(acc2[i][2]), o3 = unpk(acc2[i][3]);
        float* op = g_ao + ((size_t)(b * Sc + sg)) * Hc * D_V + h * D_V + tx * 8;
        float4 w0 = make_float4(o0.x * inv, o0.y * inv, o1.x * inv, o1.y * inv);
        float4 w1 = make_float4(o2.x * inv, o2.y * inv, o3.x * inv, o3.y * inv);
        *(float4*)op = w0;
        *(float4*)(op + 4) = w1;
    }
}

// ---------------------------------------------------------------------------
// Launch
// ---------------------------------------------------------------------------
extern "C" void kernel_launch(void* const* d_in, const int* in_sizes, int n_in,
                              void* d_out, int out_size)
{
    const float* x        = (const float*)d_in[0];
    const float* wq_a_w   = (const float*)d_in[1];
    const float* wq_a_b   = (const float*)d_in[2];
    const float* q_norm_w = (const float*)d_in[3];
    const float* wq_b_w   = (const float*)d_in[4];
    const float* wkv_a_w  = (const float*)d_in[5];
    const float* wkv_a_b  = (const float*)d_in[6];
    const float* kv_norm_w= (const float*)d_in[7];
    const float* wkv_b_w  = (const float*)d_in[8];
    const float* wo_w     = (const float*)d_in[9];
    const float* cos_t    = (const float*)d_in[10];
    const float* sin_t    = (const float*)d_in[11];
    // d_in[12] = mask (causal, recomputed inline), d_in[13] = start_pos (0)
    float* out = (float*)d_out;

    float *qa, *kva, *qln, *kvln, *q, *kv, *ao;
    cudaGetSymbolAddress((void**)&qa,   g_qa);
    cudaGetSymbolAddress((void**)&kva,  g_kva);
    cudaGetSymbolAddress((void**)&qln,  g_qln);
    cudaGetSymbolAddress((void**)&kvln, g_kvln);
    cudaGetSymbolAddress((void**)&q,    g_q);
    cudaGetSymbolAddress((void**)&kv,   g_kv);
    cudaGetSymbolAddress((void**)&ao,   g_ao);

    gemm_kernel<<<dim3(4, 32), 256>>>(x, wq_a_w, wq_a_b, qa, ROWS, Q_LORA, DIMc);
    gemm_kernel<<<dim3(5, 32), 256>>>(x, wkv_a_w, wkv_a_b, kva, ROWS, KV_LORA + D_ROPE, DIMc);
    norm_rope_kernel<<<ROWS, 256>>>(q_norm_w, kv_norm_w, cos_t, sin_t);
    gemm_kernel<<<dim3(24, 32), 256>>>(qln, wq_b_w, nullptr, q, ROWS, Hc * D_QK, Q_LORA);
    gemm_kernel<<<dim3(32, 32), 256>>>(kvln, wkv_b_w, nullptr, kv, ROWS, Hc * KV_W, KV_LORA);
    rope_q_kernel<<<ROWS * Hc * 32 / 256, 256>>>(cos_t, sin_t);

    const int smem_bytes = ATT_SMEM_FLOATS * (int)sizeof(float);
    cudaFuncSetAttribute(attn_kernel, cudaFuncAttributeMaxDynamicSharedMemorySize, smem_bytes);
    attn_kernel<<<dim3(Sc / TQ, Hc, Bc), 256, smem_bytes>>>();

    gemm_kernel<<<dim3(16, 32), 256>>>(ao, wo_w, nullptr, out, ROWS, DIMc, Hc * D_V);
}

// round 6
// speedup vs baseline: 1.0011x; 1.0011x over previous
#include <cuda_runtime.h>
#include <cuda_bf16.h>
#include <cstdint>

// ---------------------------------------------------------------------------
// MLA prefill, fp32 with packed f32x2 FFMA (sm_103a FFMA2 path).
// B=2, S=2048, DIM=2048, H=16, Q_LORA=512, KV_LORA=512,
// D_NOPE=128, D_ROPE=64, D_V=128, D_QK=192.
// ---------------------------------------------------------------------------

namespace {
constexpr int Bc = 2, Sc = 2048, DIMc = 2048, Hc = 16;
constexpr int Q_LORA = 512, KV_LORA = 512;
constexpr int D_NOPE = 128, D_ROPE = 64, D_V = 128, D_QK = 192;
constexpr int ROWS = Bc * Sc;        // 4096 tokens
constexpr int KV_W = D_NOPE + D_V;   // 256
}

// Scratch (static device arrays: allocation-free per harness rules)
__device__ float g_qa  [ROWS * Q_LORA];
__device__ float g_kva [ROWS * (KV_LORA + D_ROPE)];
__device__ float g_qln [ROWS * Q_LORA];
__device__ float g_kvln[ROWS * KV_LORA];
__device__ float g_kpe [ROWS * D_ROPE];
__device__ float g_q   [ROWS * Hc * D_QK];
__device__ float g_kv  [ROWS * Hc * KV_W];
__device__ float g_ao  [ROWS * Hc * D_V];

// ---------------------------------------------------------------------------
// f32x2 packed helpers
// ---------------------------------------------------------------------------
__device__ __forceinline__ void ffma2(uint64_t& d, uint64_t a, uint64_t b) {
    asm("fma.rn.f32x2 %0, %1, %2, %0;" : "+l"(d) : "l"(a), "l"(b));
}
__device__ __forceinline__ void fmul2(uint64_t& d, uint64_t a) {
    asm("mul.rn.f32x2 %0, %0, %1;" : "+l"(d) : "l"(a));
}
__device__ __forceinline__ uint64_t dup2(float x) {
    uint64_t r; asm("mov.b64 %0, {%1, %1};" : "=l"(r) : "f"(x)); return r;
}
__device__ __forceinline__ uint64_t pk2(float x, float y) {
    uint64_t r; asm("mov.b64 %0, {%1, %2};" : "=l"(r) : "f"(x), "f"(y)); return r;
}
__device__ __forceinline__ float2 unpk(uint64_t p) {
    float2 r; asm("mov.b64 {%0, %1}, %2;" : "=f"(r.x), "=f"(r.y) : "l"(p)); return r;
}

// ---------------------------------------------------------------------------
// GEMM: C[M,N] = A[M,K] @ W[K,N] (+ bias). 128x128 tile, BK=8, 256 threads,
// 8x8 per thread, inner product via FFMA2 packed over N (B pairs natural,
// A duplicated into both halves).
// ---------------------------------------------------------------------------
__global__ __launch_bounds__(256, 2) void gemm_kernel(
    const float* __restrict__ A, const float* __restrict__ W,
    const float* __restrict__ bias, float* __restrict__ C,
    int M, int N, int K)
{
    constexpr int BM = 128, BN = 128, BK = 8;
    __shared__ float As[BK][BM];
    __shared__ float Bs[BK][BN];

    const int tid = threadIdx.x;
    const int ty = tid >> 4, tx = tid & 15;
    const int row0 = blockIdx.y * BM;
    const int col0 = blockIdx.x * BN;

    const int a_m = tid >> 1;
    const int a_k = (tid & 1) << 2;
    const int b_k = tid >> 5;
    const int b_n = (tid & 31) << 2;

    uint64_t acc2[8][4];   // [row i][col-pair jp]; pairs over N
#pragma unroll
    for (int i = 0; i < 8; i++)
#pragma unroll
        for (int jp = 0; jp < 4; jp++) acc2[i][jp] = 0ull;

    const float* Aptr = A + (size_t)(row0 + a_m) * K + a_k;

    for (int k0 = 0; k0 < K; k0 += BK) {
        float4 av = *(const float4*)(Aptr + k0);
        As[a_k + 0][a_m] = av.x;
        As[a_k + 1][a_m] = av.y;
        As[a_k + 2][a_m] = av.z;
        As[a_k + 3][a_m] = av.w;

        const int gn = col0 + b_n;
        float4 bv = make_float4(0.f, 0.f, 0.f, 0.f);
        if (gn < N) bv = *(const float4*)(W + (size_t)(k0 + b_k) * N + gn);
        *(float4*)&Bs[b_k][b_n] = bv;
        __syncthreads();

#pragma unroll
        for (int kk = 0; kk < BK; kk++) {
            float4 a0 = *(const float4*)&As[kk][ty * 4];
            float4 a1 = *(const float4*)&As[kk][ty * 4 + 64];
            ulonglong2 bl0 = *(const ulonglong2*)&Bs[kk][tx * 4];
            ulonglong2 bl1 = *(const ulonglong2*)&Bs[kk][tx * 4 + 64];
            uint64_t bp[4] = {bl0.x, bl0.y, bl1.x, bl1.y};
            uint64_t ad[8];
            ad[0] = dup2(a0.x); ad[1] = dup2(a0.y);
            ad[2] = dup2(a0.z); ad[3] = dup2(a0.w);
            ad[4] = dup2(a1.x); ad[5] = dup2(a1.y);
            ad[6] = dup2(a1.z); ad[7] = dup2(a1.w);
#pragma unroll
            for (int i = 0; i < 8; i++)
#pragma unroll
                for (int jp = 0; jp < 4; jp++)
                    ffma2(acc2[i][jp], ad[i], bp[jp]);
        }
        __syncthreads();
    }

#pragma unroll
    for (int i = 0; i < 8; i++) {
        const int r = row0 + ty * 4 + (i < 4 ? i : 60 + i);
#pragma unroll
        for (int jj = 0; jj < 2; jj++) {
            const int c = col0 + tx * 4 + jj * 64;
            if (c < N) {
                float2 lo = unpk(acc2[i][jj * 2 + 0]);
                float2 hi = unpk(acc2[i][jj * 2 + 1]);
                float4 v = make_float4(lo.x, lo.y, hi.x, hi.y);
                if (bias) {
                    v.x += bias[c + 0]; v.y += bias[c + 1];
                    v.z += bias[c + 2]; v.w += bias[c + 3];
                }
                *(float4*)(C + (size_t)r * N + c) = v;
            }
        }
    }
}

// ---------------------------------------------------------------------------
// Fused: rmsnorm(q_a) -> g_qln; rmsnorm(kv_a[:,:512]) -> g_kvln;
// rope(kv_a[:,512:576]) -> g_kpe.  One block per token row.
// ---------------------------------------------------------------------------
__global__ __launch_bounds__(256) void norm_rope_kernel(
    const float* __restrict__ qnw, const float* __restrict__ kvnw,
    const float* __restrict__ cos_t, const float* __restrict__ sin_t)
{
    const int row = blockIdx.x;
    const int tid = threadIdx.x;
    const int s = row & (Sc - 1);
    __shared__ float red[8];

    const float* qr = g_qa + (size_t)row * Q_LORA;
    float v0 = qr[tid], v1 = qr[tid + 256];
    float ss = v0 * v0 + v1 * v1;
#pragma unroll
    for (int o = 16; o; o >>= 1) ss += __shfl_xor_sync(0xffffffffu, ss, o);
    if ((tid & 31) == 0) red[tid >> 5] = ss;
    __syncthreads();
    float tot = 0.f;
#pragma unroll
    for (int i = 0; i < 8; i++) tot += red[i];
    float scl = rsqrtf(tot * (1.0f / Q_LORA) + 1e-6f);
    g_qln[(size_t)row * Q_LORA + tid]       = v0 * scl * qnw[tid];
    g_qln[(size_t)row * Q_LORA + tid + 256] = v1 * scl * qnw[tid + 256];
    __syncthreads();

    const float* kr = g_kva + (size_t)row * (KV_LORA + D_ROPE);
    float w0 = kr[tid], w1 = kr[tid + 256];
    float ss2 = w0 * w0 + w1 * w1;
#pragma unroll
    for (int o = 16; o; o >>= 1) ss2 += __shfl_xor_sync(0xffffffffu, ss2, o);
    if ((tid & 31) == 0) red[tid >> 5] = ss2;
    __syncthreads();
    float tot2 = 0.f;
#pragma unroll
    for (int i = 0; i < 8; i++) tot2 += red[i];
    float scl2 = rsqrtf(tot2 * (1.0f / KV_LORA) + 1e-6f);
    g_kvln[(size_t)row * KV_LORA + tid]       = w0 * scl2 * kvnw[tid];
    g_kvln[(size_t)row * KV_LORA + tid + 256] = w1 * scl2 * kvnw[tid + 256];

    if (tid < 32) {
        float x0 = kr[KV_LORA + 2 * tid];
        float x1 = kr[KV_LORA + 2 * tid + 1];
        float c = cos_t[s * 32 + tid], sn = sin_t[s * 32 + tid];
        g_kpe[(size_t)row * D_ROPE + 2 * tid]     = x0 * c - x1 * sn;
        g_kpe[(size_t)row * D_ROPE + 2 * tid + 1] = x0 * sn + x1 * c;
    }
}

// ---------------------------------------------------------------------------
// RoPE on q_pe (last 64 of each head's 192), in place on g_q.
// ---------------------------------------------------------------------------
__global__ __launch_bounds__(256) void rope_q_kernel(
    const float* __restrict__ cos_t, const float* __restrict__ sin_t)
{
    const int idx = blockIdx.x * 256 + threadIdx.x;
    const int i = idx & 31;
    const int h = (idx >> 5) & 15;
    const int row = idx >> 9;
    const int s = row & (Sc - 1);
    float* p = g_q + ((size_t)row * Hc + h) * D_QK + D_NOPE + 2 * i;
    float x0 = p[0], x1 = p[1];
    float c = cos_t[s * 32 + i], sn = sin_t[s * 32 + i];
    p[0] = x0 * c - x1 * sn;
    p[1] = x0 * sn + x1 * c;
}

// ---------------------------------------------------------------------------
// Flash attention, fp32 + FFMA2. One block per (q-tile 64, head, batch).
// Row-major Q/K smem; K chunk-XOR-swizzled for conflict-free vector loads;
// scores packed over the d reduction (even/odd partials in one f32x2 reg).
// Softmax entirely in registers + half-warp shuffles.
// ---------------------------------------------------------------------------
namespace {
constexpr int TQ = 64, TK = 64;
constexpr int QROW = 192;           // Q/K row length (floats)
constexpr int PST = 66;             // P tile stride
constexpr int QS_F = TQ * QROW;     // 12288
constexpr int KS_F = TK * QROW;     // 12288
constexpr int VS_F = TK * D_V;      // 8192
constexpr int PS_F = TQ * PST;      // 4224
constexpr int ATT_SMEM_FLOATS = QS_F + KS_F + VS_F + PS_F;
constexpr float QK_SCALE = 0.07216878364870322f;  // 192^-0.5
}

__global__ __launch_bounds__(256) void attn_kernel()
{
    extern __shared__ float sm[];
    float* Qs = sm;            // [64][192] row-major (pre-scaled)
    float* Ks = Qs + QS_F;     // [64][192] row-major, chunk-swizzled
    float* Vs = Ks + KS_F;     // [64][128] row-major
    float* Ps = Vs + VS_F;     // [64][66]

    const int tid = threadIdx.x;
    const int ty = tid >> 4, tx = tid & 15;
    const int bq = gridDim.x - 1 - blockIdx.x;   // heavy tiles launch first
    const int h = blockIdx.y;
    const int b = blockIdx.z;
    const int s0 = bq * TQ;
    const int xs = tx & 7;

    // Load Q tile (pre-scaled), row-major
    const float* qbase = g_q + (((size_t)b * Sc + s0) * Hc + h) * D_QK;
    for (int idx = tid; idx < TQ * 48; idx += 256) {
        int r = idx / 48, c4 = idx - r * 48;
        float4 v = *(const float4*)(qbase + (size_t)r * Hc * D_QK + 4 * c4);
        v.x *= QK_SCALE; v.y *= QK_SCALE; v.z *= QK_SCALE; v.w *= QK_SCALE;
        *(float4*)&Qs[r * QROW + 4 * c4] = v;
    }

    float m_i[4], l_i[4];
    uint64_t acc2[4][4];
#pragma unroll
    for (int i = 0; i < 4; i++) {
        m_i[i] = -1e30f; l_i[i] = 0.f;
#pragma unroll
        for (int jp = 0; jp < 4; jp++) acc2[i][jp] = 0ull;
    }

    const float* kvbase  = g_kv  + ((size_t)b * Sc * Hc + h) * KV_W;
    const float* kpebase = g_kpe + (size_t)b * Sc * D_ROPE;

    for (int jt = 0; jt <= bq; jt++) {
        const int t0 = jt * TK;
        __syncthreads();   // smem reuse (and Q visibility on iter 0)

        // K nope part: rows c, chunks d4=0..31, XOR-swizzled
        for (int idx = tid; idx < TK * 32; idx += 256) {
            int c = idx >> 5, d4 = idx & 31;
            float4 v = *(const float4*)(kvbase + (size_t)(t0 + c) * Hc * KV_W + 4 * d4);
            *(float4*)&Ks[c * QROW + 4 * (d4 ^ ((c >> 2) & 7))] = v;
        }
        // K rope part: chunks d4=32..47
        for (int idx = tid; idx < TK * 16; idx += 256) {
            int c = idx >> 4, dq = idx & 15;
            float4 v = *(const float4*)(kpebase + (size_t)(t0 + c) * D_ROPE + 4 * dq);
            *(float4*)&Ks[c * QROW + 4 * ((32 + dq) ^ ((c >> 2) & 7))] = v;
        }
        // V tile, row-major
        for (int idx = tid; idx < TK * 32; idx += 256) {
            int c = idx >> 5, d4 = idx & 31;
            float4 v = *(const float4*)(kvbase + (size_t)(t0 + c) * Hc * KV_W + D_NOPE + 4 * d4);
            *(float4*)&Vs[c * D_V + 4 * d4] = v;
        }
        __syncthreads();

        // ---- Scores: packed over d (even/odd partials per f32x2 reg) ----
        uint64_t sf2[4][4];
#pragma unroll
        for (int i = 0; i < 4; i++)
#pragma unroll
            for (int j = 0; j < 4; j++) sf2[i][j] = 0ull;

#pragma unroll 4
        for (int cc = 0; cc < 48; cc++) {
            ulonglong2 qv[4];
#pragma unroll
            for (int i = 0; i < 4; i++)
                qv[i] = *(const ulonglong2*)&Qs[(ty * 4 + i) * QROW + 4 * cc];
            const int koff = 4 * (cc ^ xs);
            ulonglong2 kv4[4];
#pragma unroll
            for (int j = 0; j < 4; j++)
                kv4[j] = *(const ulonglong2*)&Ks[(tx * 4 + j) * QROW + koff];
#pragma unroll
            for (int i = 0; i < 4; i++)
#pragma unroll
                for (int j = 0; j < 4; j++) {
                    ffma2(sf2[i][j], qv[i].x, kv4[j].x);
                    ffma2(sf2[i][j], qv[i].y, kv4[j].y);
                }
        }

        float s[4][4];
#pragma unroll
        for (int i = 0; i < 4; i++)
#pragma unroll
            for (int j = 0; j < 4; j++) {
                float2 t = unpk(sf2[i][j]);
                s[i][j] = t.x + t.y;
            }

        // Causal mask (only the diagonal tile needs it)
        if (jt == bq) {
#pragma unroll
            for (int i = 0; i < 4; i++) {
                const int sg = s0 + ty * 4 + i;
#pragma unroll
                for (int j = 0; j < 4; j++)
                    if (t0 + tx * 4 + j > sg) s[i][j] = -1e30f;
            }
        }

        // ---- Online softmax in registers, half-warp shuffles ----
#pragma unroll
        for (int i = 0; i < 4; i++) {
            float mx = fmaxf(fmaxf(s[i][0], s[i][1]), fmaxf(s[i][2], s[i][3]));
            mx = fmaxf(mx, __shfl_xor_sync(0xffffffffu, mx, 1));
            mx = fmaxf(mx, __shfl_xor_sync(0xffffffffu, mx, 2));
            mx = fmaxf(mx, __shfl_xor_sync(0xffffffffu, mx, 4));
            mx = fmaxf(mx, __shfl_xor_sync(0xffffffffu, mx, 8));
            float mn = fmaxf(m_i[i], mx);
            float f = __expf(m_i[i] - mn);
            m_i[i] = mn;
            float p0 = __expf(s[i][0] - mn);
            float p1 = __expf(s[i][1] - mn);
            float p2 = __expf(s[i][2] - mn);
            float p3 = __expf(s[i][3] - mn);
            float sum = (p0 + p1) + (p2 + p3);
            sum += __shfl_xor_sync(0xffffffffu, sum, 1);
            sum += __shfl_xor_sync(0xffffffffu, sum, 2);
            sum += __shfl_xor_sync(0xffffffffu, sum, 4);
            sum += __shfl_xor_sync(0xffffffffu, sum, 8);
            l_i[i] = l_i[i] * f + sum;
            uint64_t fd = dup2(f);
#pragma unroll
            for (int jp = 0; jp < 4; jp++) fmul2(acc2[i][jp], fd);
            *(uint64_t*)&Ps[(ty * 4 + i) * PST + tx * 4]     = pk2(p0, p1);
            *(uint64_t*)&Ps[(ty * 4 + i) * PST + tx * 4 + 2] = pk2(p2, p3);
        }
        __syncwarp();   // P rows stay within this half-warp

        // ---- P @ V: packed over d_v (V pairs natural), p duplicated ----
#pragma unroll 2
        for (int c = 0; c < TK; c++) {
            ulonglong2 v01 = *(const ulonglong2*)&Vs[c * D_V + tx * 8];
            ulonglong2 v23 = *(const ulonglong2*)&Vs[c * D_V + tx * 8 + 4];
            uint64_t vp[4] = {v01.x, v01.y, v23.x, v23.y};
#pragma unroll
            for (int i = 0; i < 4; i++) {
                uint64_t pd = dup2(Ps[(ty * 4 + i) * PST + c]);
#pragma unroll
                for (int jp = 0; jp < 4; jp++) ffma2(acc2[i][jp], pd, vp[jp]);
            }
        }
    }

    // Epilogue
#pragma unroll
    for (int i = 0; i < 4; i++) {
        const int sg = s0 + ty * 4 + i;
        const float inv = 1.0f / l_i[i];
        float2 o0 = unpk(acc2[i][0]), o1 = unpk(acc2[i][1]);
        float2 o2 = unpk(acc2[i][2]), o3 = unpk(acc2[i][3]);
        float* op = g_ao + ((size_t)(b * Sc + sg)) * Hc * D_V + h * D_V + tx * 8;
        float4 w0 = make_float4(o0.x * inv, o0.y * inv, o1.x * inv, o1.y * inv);
        float4 w1 = make_float4(o2.x * inv, o2.y * inv, o3.x * inv, o3.y * inv);
        *(float4*)op = w0;
        *(float4*)(op + 4) = w1;
    }
}

// ---------------------------------------------------------------------------
// Launch
// ---------------------------------------------------------------------------
extern "C" void kernel_launch(void* const* d_in, const int* in_sizes, int n_in,
                              void* d_out, int out_size)
{
    const float* x        = (const float*)d_in[0];
    const float* wq_a_w   = (const float*)d_in[1];
    const float* wq_a_b   = (const float*)d_in[2];
    const float* q_norm_w = (const float*)d_in[3];
    const float* wq_b_w   = (const float*)d_in[4];
    const float* wkv_a_w  = (const float*)d_in[5];
    const float* wkv_a_b  = (const float*)d_in[6];
    const float* kv_norm_w= (const float*)d_in[7];
    const float* wkv_b_w  = (const float*)d_in[8];
    const float* wo_w     = (const float*)d_in[9];
    const float* cos_t    = (const float*)d_in[10];
    const float* sin_t    = (const float*)d_in[11];
    // d_in[12] = mask (causal, recomputed inline), d_in[13] = start_pos (0)
    float* out = (float*)d_out;

    float *qa, *kva, *qln, *kvln, *q, *kv, *ao;
    cudaGetSymbolAddress((void**)&qa,   g_qa);
    cudaGetSymbolAddress((void**)&kva,  g_kva);
    cudaGetSymbolAddress((void**)&qln,  g_qln);
    cudaGetSymbolAddress((void**)&kvln, g_kvln);
    cudaGetSymbolAddress((void**)&q,    g_q);
    cudaGetSymbolAddress((void**)&kv,   g_kv);
    cudaGetSymbolAddress((void**)&ao,   g_ao);

    gemm_kernel<<<dim3(4, 32), 256>>>(x, wq_a_w, wq_a_b, qa, ROWS, Q_LORA, DIMc);
    gemm_kernel<<<dim3(5, 32), 256>>>(x, wkv_a_w, wkv_a_b, kva, ROWS, KV_LORA + D_ROPE, DIMc);
    norm_rope_kernel<<<ROWS, 256>>>(q_norm_w, kv_norm_w, cos_t, sin_t);
    gemm_kernel<<<dim3(24, 32), 256>>>(qln, wq_b_w, nullptr, q, ROWS, Hc * D_QK, Q_LORA);
    gemm_kernel<<<dim3(32, 32), 256>>>(kvln, wkv_b_w, nullptr, kv, ROWS, Hc * KV_W, KV_LORA);
    rope_q_kernel<<<ROWS * Hc * 32 / 256, 256>>>(cos_t, sin_t);

    const int smem_bytes = ATT_SMEM_FLOATS * (int)sizeof(float);
    cudaFuncSetAttribute(attn_kernel, cudaFuncAttributeMaxDynamicSharedMemorySize, smem_bytes);
    attn_kernel<<<dim3(Sc / TQ, Hc, Bc), 256, smem_bytes>>>();

    gemm_kernel<<<dim3(16, 32), 256>>>(ao, wo_w, nullptr, out, ROWS, DIMc, Hc * D_V);
}